// round 15
// baseline (speedup 1.0000x reference)
#include <cuda_runtime.h>
#include <cuda_bf16.h>
#include <cuda_fp16.h>
#include <cstdint>

#define N_  64
#define C_  64
#define T_  128
#define V_  25
#define H_  3
#define O_  192

typedef unsigned long long ull;

// ---------------- scratch ----------------
__device__ __align__(16) float g_pe[C_*V_];
__device__ __align__(16) float g_attpart[64*8*300*26];
__device__ __align__(16) float g_att[N_*H_*V_*V_];
__device__ __align__(16) float g_z[N_*C_*T_*V_];
__device__ __align__(16) float g_bnpart[2048*128];
__device__ __align__(16) float g_bn[128];
// conv W per dv: [co=64][colp=200] fp16 = 25600 B = 1600 uint4
__device__ __align__(16) uint4 g_Wimg[5][1600];
// QKV W image: [term hi/lo][o=192][c=72pad] fp16 = 55296 B = 3456 uint4
__device__ __align__(16) uint4 g_WqkvImg[3456];

// ---------------- f32x2 helpers ----------------
static __device__ __forceinline__ ull pack2(float a, float b){
  ull r; asm("mov.b64 %0, {%1, %2};" : "=l"(r) : "f"(a), "f"(b)); return r;
}
static __device__ __forceinline__ void fma2(ull& d, ull a, ull b){
  asm("fma.rn.f32x2 %0, %1, %2, %0;" : "+l"(d) : "l"(a), "l"(b));
}
static __device__ __forceinline__ float lo2(ull v){ return __uint_as_float((unsigned)v); }
static __device__ __forceinline__ float hi2(ull v){ return __uint_as_float((unsigned)(v>>32)); }

// ---------------- portable tensor-core helpers (sm_80+ baseline PTX) ----------------
static __device__ __forceinline__ uint32_t smem_to_u32(const void* p) {
  uint32_t a;
  asm("{ .reg .u64 t; cvta.to.shared.u64 t, %1; cvt.u32.u64 %0, t; }" : "=r"(a) : "l"(p));
  return a;
}
static __device__ __forceinline__ void ldm_x4(uint32_t* r, uint32_t addr){
  asm volatile("ldmatrix.sync.aligned.m8n8.x4.shared.b16 {%0,%1,%2,%3}, [%4];"
    : "=r"(r[0]), "=r"(r[1]), "=r"(r[2]), "=r"(r[3]) : "r"(addr));
}
static __device__ __forceinline__ void mma_f16(float* d, const uint32_t* a, const uint32_t* b){
  asm volatile("mma.sync.aligned.m16n8k16.row.col.f32.f16.f16.f32 "
    "{%0,%1,%2,%3}, {%4,%5,%6,%7}, {%8,%9}, {%0,%1,%2,%3};"
    : "+f"(d[0]), "+f"(d[1]), "+f"(d[2]), "+f"(d[3])
    : "r"(a[0]), "r"(a[1]), "r"(a[2]), "r"(a[3]), "r"(b[0]), "r"(b[1]));
}

// ---------------- init ----------------
__global__ void k_init(const float* __restrict__ Wqkv, const float* __restrict__ Wout) {
  const int stride = gridDim.x * blockDim.x;
  const int i0 = blockIdx.x * blockDim.x + threadIdx.x;
  for (int i = i0; i < C_*V_; i += stride) {
    int c = i / V_, v = i - (i / V_) * V_;
    int ii = c >> 1;
    float dv = __expf(-(2.0f * ii) * (logf(10000.0f) / 64.0f));
    float ang = (float)v * dv;
    g_pe[i] = (c & 1) ? cosf(ang) : sinf(ang);
  }
  {
    __half* wb = (__half*)g_WqkvImg;
    for (int i = i0; i < 2*192*72; i += stride) {
      int term = i / 13824; int r = i - term*13824;
      int o = r / 72, c = r - (r/72)*72;
      float w = (c < 64) ? Wqkv[o*64 + c] : 0.f;
      __half hb = __float2half(w);
      wb[i] = (term == 0) ? hb : __float2half(w - __half2float(hb));
    }
  }
  {
    __half* wb = (__half*)g_Wimg;
    for (int i = i0; i < 5*64*200; i += stride) {
      int dv = i / 12800; int r = i - dv*12800;
      int co = r / 200; int cp = r - co*200;
      float w = (cp < 192) ? Wout[co*960 + cp*5 + dv] : 0.f;
      wb[i] = __float2half(w);
    }
  }
}

// ---------------- kernel A: QK GEMM (mma.sync fp16 3-term) + scalar Gram ----------------
// qk pitch 112 floats (448B rows, tl-groups of 28) -> LDS.128 Gram reads.
#define QKP 112
__global__ __launch_bounds__(384, 1) void k_qkatt(const float* __restrict__ x,
                                                  const float* __restrict__ bqkv) {
  extern __shared__ char sqc[];
  const uint32_t sbase = smem_to_u32(sqc);
  float* qk = (float*)(sqc + 87552);
  const int tid = threadIdx.x;
  const int wid = tid >> 5, lane = tid & 31;
  const int n = blockIdx.y, tc = blockIdx.x;
  const int t0 = tc * 16;

  for (int i = tid; i < 3456; i += 384) ((uint4*)sqc)[i] = g_WqkvImg[i];
  // zero B region (32256 B) + qk (86016 B)
  for (int i = tid; i < 8064; i += 384) ((float*)(sqc + 55296))[i] = 0.f;
  for (int i = tid; i < 21504; i += 384) qk[i] = 0.f;
  __syncthreads();

  {
    const float* xg = x + (((size_t)n*C_)*T_ + t0)*V_;
    for (int i = tid; i < 6400; i += 384) {
      int c = (i & 7) | (((i >> 5) & 7) << 3);
      int r = ((i >> 3) & 3) | ((i >> 8) << 2);
      int tl = r / 25, v = r - tl*25;
      float xv = xg[(size_t)c*3200 + r] + g_pe[c*25 + v];
      int boff = (tl*28 + v)*144 + c*2;
      __half hb = __float2half(xv);
      *(__half*)(sqc + 55296 + boff) = hb;
      *(__half*)(sqc + 71424 + boff) = __float2half(xv - __half2float(hb));
    }
  }
  __syncthreads();

  const int m0 = wid * 16;
  const uint32_t aoff = (uint32_t)((m0 + (lane&7) + ((lane>>3)&1)*8)*144 + (lane>>4)*16);
  uint32_t ah[4][4], al[4][4];
  #pragma unroll
  for (int kc = 0; kc < 4; ++kc) {
    ldm_x4(ah[kc], sbase + aoff + kc*32);
    ldm_x4(al[kc], sbase + 27648u + aoff + kc*32);
  }
  const int g = lane >> 2, c0 = (lane&3)*2;
  const float bq0 = bqkv[m0 + g];
  const float bq1 = bqkv[m0 + g + 8];

  const int grow = tid >> 2, gcq = tid & 3;
  const bool gact = (tid < 300);
  const int gh = grow / 25, gu = grow - (grow/25)*25;
  ull gacc[13];
  #pragma unroll
  for (int j = 0; j < 13; ++j) gacc[j] = 0ULL;

  const uint32_t bboff = (uint32_t)(((lane&7) + ((lane>>4)&1)*8)*144 + ((lane>>3)&1)*16);

  for (int ck = 0; ck < 4; ++ck) {
    float d[14][4];
    #pragma unroll
    for (int nt = 0; nt < 14; ++nt)
      #pragma unroll
      for (int j = 0; j < 4; ++j) d[nt][j] = 0.f;

    #pragma unroll
    for (int p = 0; p < 7; ++p) {
      const uint32_t bb = sbase + 55296u + (uint32_t)p*2304u + bboff;
      #pragma unroll
      for (int kc = 0; kc < 4; ++kc) {
        uint32_t bh[4], bl[4];
        ldm_x4(bh, bb + kc*32);
        ldm_x4(bl, bb + 16128u + kc*32);
        mma_f16(d[2*p],   ah[kc], bh);
        mma_f16(d[2*p+1], ah[kc], bh + 2);
        mma_f16(d[2*p],   ah[kc], bl);
        mma_f16(d[2*p+1], ah[kc], bl + 2);
        mma_f16(d[2*p],   al[kc], bh);
        mma_f16(d[2*p+1], al[kc], bh + 2);
      }
    }
    #pragma unroll
    for (int nt = 0; nt < 14; ++nt) {
      int col = nt*8 + c0;
      float* r0 = qk + (m0 + g)*QKP + col;
      float* r1 = qk + (m0 + g + 8)*QKP + col;
      r0[0] = d[nt][0] + bq0; r0[1] = d[nt][1] + bq0;
      r1[0] = d[nt][2] + bq1; r1[1] = d[nt][3] + bq1;
    }
    __syncthreads();

    if (gact) {
      #pragma unroll
      for (int tl = 0; tl < 4; ++tl) {
        #pragma unroll
        for (int c8 = 0; c8 < 8; ++c8) {
          int c = gcq*8 + c8;
          float qv = qk[(gh*32 + c)*QKP + tl*28 + gu];
          ull q2 = pack2(qv, qv);
          const float* kr = qk + (96 + gh*32 + c)*QKP + tl*28;
          const ulonglong2* kp2 = (const ulonglong2*)kr;
          #pragma unroll
          for (int j = 0; j < 6; ++j) {
            ulonglong2 w = kp2[j];
            fma2(gacc[2*j],   q2, w.x);
            fma2(gacc[2*j+1], q2, w.y);
          }
          fma2(gacc[12], q2, ((const ull*)kr)[12]);
        }
      }
    }
    if (ck < 3) {
      const float* xg = x + (((size_t)n*C_)*T_ + t0 + (ck+1)*4)*V_;
      for (int i = tid; i < 6400; i += 384) {
        int c = (i & 7) | (((i >> 5) & 7) << 3);
        int r = ((i >> 3) & 3) | ((i >> 8) << 2);
        int tl = r / 25, v = r - tl*25;
        float xv = xg[(size_t)c*3200 + r] + g_pe[c*25 + v];
        int boff = (tl*28 + v)*144 + c*2;
        __half hb = __float2half(xv);
        *(__half*)(sqc + 55296 + boff) = hb;
        *(__half*)(sqc + 71424 + boff) = __float2half(xv - __half2float(hb));
      }
    }
    __syncthreads();
  }

  if (gact) {
    ull* op = (ull*)(g_attpart + ((size_t)(n*8 + tc)*300 + tid)*26);
    #pragma unroll
    for (int j = 0; j < 13; ++j) op[j] = gacc[j];
  }
}

// ---------------- kernel A2 ----------------
__global__ void k_att2(const float* __restrict__ alphas, const float* __restrict__ att0s) {
  int i = blockIdx.x * blockDim.x + threadIdx.x;
  if (i >= N_*1875) return;
  int n = i / 1875, r = i - n*1875;
  int h = r / 625, rr = r - h*625;
  int u = rr / 25, v = rr - (rr/25)*25;
  int row = h*25 + u;
  float s = 0.f;
  #pragma unroll
  for (int tc = 0; tc < 8; ++tc)
    #pragma unroll
    for (int cq = 0; cq < 4; ++cq)
      s += g_attpart[((size_t)(n*8 + tc)*300 + row*4 + cq)*26 + v];
  g_att[i] = tanhf(s * (1.0f/4096.0f)) * alphas[h] + att0s[r];
}

// ---------------- kernel B: att-apply (FFMA2) + conv (mma.sync fp16) + BN partials ----------------
// grid (32 tc, 64 n), 512 threads, 2 CTAs/SM. smem total 110800 B.
__global__ __launch_bounds__(512, 2) void k_main(const float* __restrict__ x,
                                                 const float* __restrict__ bout) {
  extern __shared__ char smc[];
  const uint32_t sbase = smem_to_u32(smc);
  float* satt = (float*)(smc + 102400);
  float* sx   = (float*)(smc + 51200);

  const int tid = threadIdx.x;
  const int wid = tid >> 5, lane = tid & 31;
  const int n = blockIdx.y;
  const int t0 = blockIdx.x * 4;

  for (int i = tid; i < 3200; i += 512) ((uint4*)smc)[i] = make_uint4(0,0,0,0);

  for (int i = tid; i < 1875; i += 512) {
    int h = i / 625, r = i - h*625;
    int u = r / 25, v = r - (r/25)*25;
    satt[(h*25 + u)*28 + v] = g_att[(size_t)n*1875 + i];
  }
  for (int i = tid; i < 225; i += 512) { int row = i/3, c = 25 + (i - (i/3)*3); satt[row*28 + c] = 0.f; }

  {
    const float* xg = x + (((size_t)n*C_)*T_ + t0)*V_;
    for (int i = tid; i < 6400; i += 512) {
      int ci = i / 100, r = i - ci*100;
      sx[ci*101 + r] = xg[(size_t)ci*3200 + r];
    }
  }
  __syncthreads();

  // Phase 1: y[ch][t4][v] -> A[t4*32 + v + 2][ch] as fp16 (LDS.128 att reads)
  #pragma unroll
  for (int rep = 0; rep < 2; ++rep) {
    int task = tid + 512*rep;
    if (task < 768) {
      int h = task >> 8, t4 = (task >> 6) & 3, ci = task & 63;
      ull a2[13];
      #pragma unroll
      for (int j = 0; j < 13; ++j) a2[j] = 0ULL;
      const float* sxp = sx + ci*101 + t4*25;
      const float* ap0 = satt + h*25*28;
      #pragma unroll
      for (int u = 0; u < 25; ++u) {
        float xv = sxp[u];
        ull xp = pack2(xv, xv);
        const float* arow = ap0 + u*28;
        const ulonglong2* ar2 = (const ulonglong2*)arow;
        #pragma unroll
        for (int q = 0; q < 6; ++q) {
          ulonglong2 w = ar2[q];
          fma2(a2[2*q],   xp, w.x);
          fma2(a2[2*q+1], xp, w.y);
        }
        fma2(a2[12], xp, ((const ull*)arow)[12]);
      }
      const int ch = h*64 + ci;
      char* aro = smc + (t4*32 + 2)*400 + ch*2;
      #pragma unroll
      for (int v = 0; v < 25; ++v) {
        float yv = (v & 1) ? hi2(a2[v >> 1]) : lo2(a2[v >> 1]);
        *(__half*)(aro + v*400) = __float2half(yv);
      }
    }
  }
  __syncthreads();

  for (int i = tid; i < 3200; i += 512) {
    int b = i >= 1600;
    ((uint4*)(smc + 51200))[i] = g_Wimg[b][i - b*1600];
  }
  __syncthreads();

  // Phase 2: conv GEMM (single fp16 term)
  const int mband = wid >> 1, nhalf = wid & 1;
  const int r8 = lane & 7;
  const uint32_t aoff  = (uint32_t)((mband*16 + r8 + ((lane>>3)&1)*8)*400 + (lane>>4)*16);
  const uint32_t boff0 = (uint32_t)((nhalf*32 + r8 + ((lane>>4)&1)*8)*400 + ((lane>>3)&1)*16);

  float d[4][4];
  #pragma unroll
  for (int j = 0; j < 4; ++j)
    #pragma unroll
    for (int k = 0; k < 4; ++k) d[j][k] = 0.f;

  for (int dv = 0; dv < 5; ++dv) {
    const int b = dv & 1;
    const uint32_t abase = sbase + aoff + (uint32_t)dv*400u;
    const uint32_t bbase = sbase + 51200u + (uint32_t)b*25600u + boff0;
    #pragma unroll
    for (int kc = 0; kc < 12; ++kc) {
      uint32_t ah[4], b0[4], b1[4];
      ldm_x4(ah, abase + kc*32);
      ldm_x4(b0, bbase + kc*32);
      ldm_x4(b1, bbase + 6400 + kc*32);
      mma_f16(d[0], ah, b0);
      mma_f16(d[1], ah, b0 + 2);
      mma_f16(d[2], ah, b1);
      mma_f16(d[3], ah, b1 + 2);
    }
    if (dv < 3) {
      __syncthreads();
      for (int i = tid; i < 1600; i += 512)
        ((uint4*)(smc + 51200 + b*25600))[i] = g_Wimg[dv + 2][i];
      __syncthreads();
    }
  }

  // Epilogue: predicated direct stores with bias + BN partial sums
  float bs[8], bq[8];
  {
    const int g = lane >> 2;
    const int m0 = mband*16 + g;
    const int m1 = m0 + 8;
    const int t40 = m0 >> 5, v0 = m0 & 31;
    const int t41 = m1 >> 5, v1 = m1 & 31;
    const size_t zb = (size_t)n*204800;
    #pragma unroll
    for (int j = 0; j < 4; ++j) {
      int co = nhalf*32 + j*8 + (lane & 3)*2;
      float b0v = bout[co], b1v = bout[co + 1];
      float s0 = 0.f, q0 = 0.f, s1 = 0.f, q1 = 0.f;
      if (v0 < 25) {
        size_t base = zb + (size_t)co*3200 + (t0 + t40)*25 + v0;
        float z0 = d[j][0] + b0v, z1 = d[j][1] + b1v;
        g_z[base]        = z0;
        g_z[base + 3200] = z1;
        s0 += z0; q0 += z0*z0; s1 += z1; q1 += z1*z1;
      }
      if (v1 < 25) {
        size_t base = zb + (size_t)co*3200 + (t0 + t41)*25 + v1;
        float z2 = d[j][2] + b0v, z3 = d[j][3] + b1v;
        g_z[base]        = z2;
        g_z[base + 3200] = z3;
        s0 += z2; q0 += z2*z2; s1 += z3; q1 += z3*z3;
      }
      bs[2*j] = s0; bq[2*j] = q0; bs[2*j+1] = s1; bq[2*j+1] = q1;
    }
  }
  #pragma unroll
  for (int off = 4; off <= 16; off <<= 1) {
    #pragma unroll
    for (int k = 0; k < 8; ++k) {
      bs[k] += __shfl_xor_sync(0xffffffffu, bs[k], off);
      bq[k] += __shfl_xor_sync(0xffffffffu, bq[k], off);
    }
  }
  __syncthreads();
  float* sred  = (float*)smc;
  float* sred2 = (float*)(smc + 4096);
  if ((lane >> 2) == 0) {
    #pragma unroll
    for (int j = 0; j < 4; ++j) {
      int col = nhalf*32 + j*8 + (lane & 3)*2;
      sred[wid*64 + col]      = bs[2*j];
      sred[wid*64 + col + 1]  = bs[2*j+1];
      sred2[wid*64 + col]     = bq[2*j];
      sred2[wid*64 + col + 1] = bq[2*j+1];
    }
  }
  __syncthreads();
  {
    const int cta = blockIdx.y*32 + blockIdx.x;
    if (tid < 64) {
      float s = 0.f;
      #pragma unroll
      for (int r = 0; r < 16; ++r) s += sred[r*64 + tid];
      g_bnpart[(size_t)cta*128 + tid] = s;
    } else if (tid < 128) {
      float s = 0.f;
      #pragma unroll
      for (int r = 0; r < 16; ++r) s += sred2[r*64 + tid - 64];
      g_bnpart[(size_t)cta*128 + tid] = s;
    }
  }
}

// ---------------- kernel C: BN reduce (2048 CTA partials) ----------------
__global__ void k_bnred(const float* __restrict__ gamma, const float* __restrict__ beta) {
  __shared__ float s[4][128];
  __shared__ float tot[128];
  const int tid = threadIdx.x;           // 512
  const int slot = tid & 127, part = tid >> 7;
  float sum = 0.f;
  for (int b = part; b < 2048; b += 4) sum += g_bnpart[(size_t)b*128 + slot];
  s[part][slot] = sum;
  __syncthreads();
  if (tid < 128) tot[tid] = s[0][tid] + s[1][tid] + s[2][tid] + s[3][tid];
  __syncthreads();
  if (tid < 64) {
    const float inv = 1.0f / 204800.0f;
    float mean = tot[tid] * inv;
    float var  = tot[64 + tid] * inv - mean*mean;
    float a = gamma[tid] * rsqrtf(var + 1e-5f);
    g_bn[tid]      = a;
    g_bn[64 + tid] = beta[tid] - mean * a;
  }
}

// ---------------- kernel D: epilogue ----------------
__global__ void k_out(const float* __restrict__ x, float* __restrict__ out) {
  const float4* z4 = (const float4*)g_z;
  const float4* x4 = (const float4*)x;
  float4* o4 = (float4*)out;
  const int total = (N_*C_*T_*V_) / 4;
  for (int i = blockIdx.x*blockDim.x + threadIdx.x; i < total; i += gridDim.x*blockDim.x) {
    int c = (i / 800) & 63;
    float a = g_bn[c], b = g_bn[64 + c];
    float4 z = z4[i], xx = x4[i], r;
    float v;
    v = z.x*a + b + xx.x; r.x = fmaxf(v, 0.1f*v);
    v = z.y*a + b + xx.y; r.y = fmaxf(v, 0.1f*v);
    v = z.z*a + b + xx.z; r.z = fmaxf(v, 0.1f*v);
    v = z.w*a + b + xx.w; r.w = fmaxf(v, 0.1f*v);
    o4[i] = r;
  }
}

// ---------------- launch ----------------
extern "C" void kernel_launch(void* const* d_in, const int* in_sizes, int n_in,
                              void* d_out, int out_size) {
  const float* x      = (const float*)d_in[0];
  const float* Wqkv   = (const float*)d_in[1];
  const float* bqkv   = (const float*)d_in[2];
  const float* alphas = (const float*)d_in[3];
  const float* att0s  = (const float*)d_in[4];
  const float* Wout   = (const float*)d_in[5];
  const float* bout   = (const float*)d_in[6];
  const float* gamma  = (const float*)d_in[7];
  const float* beta   = (const float*)d_in[8];
  float* out = (float*)d_out;

  cudaFuncSetAttribute(k_qkatt, cudaFuncAttributeMaxDynamicSharedMemorySize, 173568);
  cudaFuncSetAttribute(k_main,  cudaFuncAttributeMaxDynamicSharedMemorySize, 110800);

  k_init<<<64, 256>>>(Wqkv, Wout);
  k_qkatt<<<dim3(8, 64), 384, 173568>>>(x, bqkv);
  k_att2<<<(N_*1875 + 255)/256, 256>>>(alphas, att0s);
  k_main<<<dim3(32, 64), 512, 110800>>>(x, bout);
  k_bnred<<<1, 512>>>(gamma, beta);
  k_out<<<4096, 256>>>(x, out);
}

// round 16
// speedup vs baseline: 1.2837x; 1.2837x over previous
#include <cuda_runtime.h>
#include <cuda_bf16.h>
#include <cuda_fp16.h>
#include <cstdint>

#define N_  64
#define C_  64
#define T_  128
#define V_  25
#define H_  3
#define O_  192

typedef unsigned long long ull;

// ---------------- scratch ----------------
__device__ __align__(16) float g_pe[C_*V_];
__device__ __align__(16) float g_attpart[64*8*300*26];
__device__ __align__(16) float g_att[N_*H_*V_*V_];
__device__ __align__(16) float g_z[N_*C_*T_*V_];
__device__ __align__(16) float g_bnpart[2048*128];
__device__ __align__(16) float g_bn[128];
// conv W per dv: [co=64][colp=200] fp16 = 25600 B = 1600 uint4
__device__ __align__(16) uint4 g_Wimg[5][1600];
// QKV W image: [term hi/lo][o=192][c=72pad] fp16 = 55296 B = 3456 uint4
__device__ __align__(16) uint4 g_WqkvImg[3456];

// ---------------- f32x2 helpers ----------------
static __device__ __forceinline__ ull pack2(float a, float b){
  ull r; asm("mov.b64 %0, {%1, %2};" : "=l"(r) : "f"(a), "f"(b)); return r;
}
static __device__ __forceinline__ void fma2(ull& d, ull a, ull b){
  asm("fma.rn.f32x2 %0, %1, %2, %0;" : "+l"(d) : "l"(a), "l"(b));
}
static __device__ __forceinline__ float lo2(ull v){ return __uint_as_float((unsigned)v); }
static __device__ __forceinline__ float hi2(ull v){ return __uint_as_float((unsigned)(v>>32)); }

// ---------------- portable tensor-core helpers (sm_80+ baseline PTX) ----------------
static __device__ __forceinline__ uint32_t smem_to_u32(const void* p) {
  uint32_t a;
  asm("{ .reg .u64 t; cvta.to.shared.u64 t, %1; cvt.u32.u64 %0, t; }" : "=r"(a) : "l"(p));
  return a;
}
static __device__ __forceinline__ void ldm_x4(uint32_t* r, uint32_t addr){
  asm volatile("ldmatrix.sync.aligned.m8n8.x4.shared.b16 {%0,%1,%2,%3}, [%4];"
    : "=r"(r[0]), "=r"(r[1]), "=r"(r[2]), "=r"(r[3]) : "r"(addr));
}
static __device__ __forceinline__ void mma_f16(float* d, const uint32_t* a, const uint32_t* b){
  asm volatile("mma.sync.aligned.m16n8k16.row.col.f32.f16.f16.f32 "
    "{%0,%1,%2,%3}, {%4,%5,%6,%7}, {%8,%9}, {%0,%1,%2,%3};"
    : "+f"(d[0]), "+f"(d[1]), "+f"(d[2]), "+f"(d[3])
    : "r"(a[0]), "r"(a[1]), "r"(a[2]), "r"(a[3]), "r"(b[0]), "r"(b[1]));
}
static __device__ __forceinline__ void cp_async16(uint32_t smem_dst, const void* gsrc){
  asm volatile("cp.async.cg.shared.global [%0], [%1], 16;"
    :: "r"(smem_dst), "l"(gsrc) : "memory");
}

// ---------------- init ----------------
__global__ void k_init(const float* __restrict__ Wqkv, const float* __restrict__ Wout) {
  const int stride = gridDim.x * blockDim.x;
  const int i0 = blockIdx.x * blockDim.x + threadIdx.x;
  for (int i = i0; i < C_*V_; i += stride) {
    int c = i / V_, v = i - (i / V_) * V_;
    int ii = c >> 1;
    float dv = __expf(-(2.0f * ii) * (logf(10000.0f) / 64.0f));
    float ang = (float)v * dv;
    g_pe[i] = (c & 1) ? cosf(ang) : sinf(ang);
  }
  {
    __half* wb = (__half*)g_WqkvImg;
    for (int i = i0; i < 2*192*72; i += stride) {
      int term = i / 13824; int r = i - term*13824;
      int o = r / 72, c = r - (r/72)*72;
      float w = (c < 64) ? Wqkv[o*64 + c] : 0.f;
      __half hb = __float2half(w);
      wb[i] = (term == 0) ? hb : __float2half(w - __half2float(hb));
    }
  }
  {
    __half* wb = (__half*)g_Wimg;
    for (int i = i0; i < 5*64*200; i += stride) {
      int dv = i / 12800; int r = i - dv*12800;
      int co = r / 200; int cp = r - co*200;
      float w = (cp < 192) ? Wout[co*960 + cp*5 + dv] : 0.f;
      wb[i] = __float2half(w);
    }
  }
}

// ---------------- kernel A: QK GEMM (mma.sync fp16 3-term) + scalar Gram ----------------
// round-13 geometry: qk pitch 106 (stride 10 mod 32 -> conflict-light LDS.64 Gram)
#define QKP 106
__global__ __launch_bounds__(384, 1) void k_qkatt(const float* __restrict__ x,
                                                  const float* __restrict__ bqkv) {
  extern __shared__ char sqc[];
  const uint32_t sbase = smem_to_u32(sqc);
  float* qk = (float*)(sqc + 87552);
  const int tid = threadIdx.x;
  const int wid = tid >> 5, lane = tid & 31;
  const int n = blockIdx.y, tc = blockIdx.x;
  const int t0 = tc * 16;

  for (int i = tid; i < 3456; i += 384) ((uint4*)sqc)[i] = g_WqkvImg[i];

  {
    const float* xg = x + (((size_t)n*C_)*T_ + t0)*V_;
    for (int i = tid; i < 6400; i += 384) {
      int c = (i & 7) | (((i >> 5) & 7) << 3);
      int r = ((i >> 3) & 3) | ((i >> 8) << 2);
      int tl = r / 25, v = r - tl*25;
      float xv = xg[(size_t)c*3200 + r] + g_pe[c*25 + v];
      int boff = (tl*26 + v)*144 + c*2;
      __half hb = __float2half(xv);
      *(__half*)(sqc + 55296 + boff) = hb;
      *(__half*)(sqc + 71424 + boff) = __float2half(xv - __half2float(hb));
    }
  }
  __syncthreads();

  const int m0 = wid * 16;
  const uint32_t aoff = (uint32_t)((m0 + (lane&7) + ((lane>>3)&1)*8)*144 + (lane>>4)*16);
  uint32_t ah[4][4], al[4][4];
  #pragma unroll
  for (int kc = 0; kc < 4; ++kc) {
    ldm_x4(ah[kc], sbase + aoff + kc*32);
    ldm_x4(al[kc], sbase + 27648u + aoff + kc*32);
  }
  const int g = lane >> 2, c0 = (lane&3)*2;
  const float bq0 = bqkv[m0 + g];
  const float bq1 = bqkv[m0 + g + 8];

  const int grow = tid >> 2, gcq = tid & 3;
  const bool gact = (tid < 300);
  const int gh = grow / 25, gu = grow - (grow/25)*25;
  ull gacc[13];
  #pragma unroll
  for (int j = 0; j < 13; ++j) gacc[j] = 0ULL;

  const uint32_t bboff = (uint32_t)(((lane&7) + ((lane>>4)&1)*8)*144 + ((lane>>3)&1)*16);

  for (int ck = 0; ck < 4; ++ck) {
    float d[14][4];
    #pragma unroll
    for (int nt = 0; nt < 14; ++nt)
      #pragma unroll
      for (int j = 0; j < 4; ++j) d[nt][j] = 0.f;

    #pragma unroll
    for (int p = 0; p < 7; ++p) {
      const uint32_t bb = sbase + 55296u + (uint32_t)p*2304u + bboff;
      #pragma unroll
      for (int kc = 0; kc < 4; ++kc) {
        uint32_t bh[4], bl[4];
        ldm_x4(bh, bb + kc*32);
        ldm_x4(bl, bb + 16128u + kc*32);
        mma_f16(d[2*p],   ah[kc], bh);
        mma_f16(d[2*p+1], ah[kc], bh + 2);
        mma_f16(d[2*p],   ah[kc], bl);
        mma_f16(d[2*p+1], ah[kc], bl + 2);
        mma_f16(d[2*p],   al[kc], bh);
        mma_f16(d[2*p+1], al[kc], bh + 2);
      }
    }
    #pragma unroll
    for (int nt = 0; nt < 13; ++nt) {
      int col = nt*8 + c0;
      float* r0 = qk + (m0 + g)*QKP + col;
      float* r1 = qk + (m0 + g + 8)*QKP + col;
      r0[0] = d[nt][0] + bq0; r0[1] = d[nt][1] + bq0;
      r1[0] = d[nt][2] + bq1; r1[1] = d[nt][3] + bq1;
    }
    __syncthreads();

    if (gact) {
      #pragma unroll
      for (int tl = 0; tl < 4; ++tl) {
        #pragma unroll
        for (int c8 = 0; c8 < 8; ++c8) {
          int c = gcq*8 + c8;
          float qv = qk[(gh*32 + c)*QKP + tl*26 + gu];
          ull q2 = pack2(qv, qv);
          const ull* kp = (const ull*)(qk + (96 + gh*32 + c)*QKP) + tl*13;
          #pragma unroll
          for (int j = 0; j < 13; ++j) fma2(gacc[j], q2, kp[j]);
        }
      }
    }
    if (ck < 3) {
      const float* xg = x + (((size_t)n*C_)*T_ + t0 + (ck+1)*4)*V_;
      for (int i = tid; i < 6400; i += 384) {
        int c = (i & 7) | (((i >> 5) & 7) << 3);
        int r = ((i >> 3) & 3) | ((i >> 8) << 2);
        int tl = r / 25, v = r - tl*25;
        float xv = xg[(size_t)c*3200 + r] + g_pe[c*25 + v];
        int boff = (tl*26 + v)*144 + c*2;
        __half hb = __float2half(xv);
        *(__half*)(sqc + 55296 + boff) = hb;
        *(__half*)(sqc + 71424 + boff) = __float2half(xv - __half2float(hb));
      }
    }
    __syncthreads();
  }

  if (gact) {
    ull* op = (ull*)(g_attpart + ((size_t)(n*8 + tc)*300 + tid)*26);
    #pragma unroll
    for (int j = 0; j < 13; ++j) op[j] = gacc[j];
  }
}

// ---------------- kernel A2 ----------------
__global__ void k_att2(const float* __restrict__ alphas, const float* __restrict__ att0s) {
  int i = blockIdx.x * blockDim.x + threadIdx.x;
  if (i >= N_*1875) return;
  int n = i / 1875, r = i - n*1875;
  int h = r / 625, rr = r - h*625;
  int u = rr / 25, v = rr - (rr/25)*25;
  int row = h*25 + u;
  float s = 0.f;
  #pragma unroll
  for (int tc = 0; tc < 8; ++tc)
    #pragma unroll
    for (int cq = 0; cq < 4; ++cq)
      s += g_attpart[((size_t)(n*8 + tc)*300 + row*4 + cq)*26 + v];
  g_att[i] = tanhf(s * (1.0f/4096.0f)) * alphas[h] + att0s[r];
}

// ---------------- kernel B: att-apply (FFMA2) + conv (mma.sync fp16) + BN partials ----------------
// grid (32 tc, 64 n), 512 threads, 2 CTAs/SM. smem total 110800 B.
// B reload pipelined with cp.async (one-iteration lookahead).
__global__ __launch_bounds__(512, 2) void k_main(const float* __restrict__ x,
                                                 const float* __restrict__ bout) {
  extern __shared__ char smc[];
  const uint32_t sbase = smem_to_u32(smc);
  float* satt = (float*)(smc + 102400);
  float* sx   = (float*)(smc + 51200);

  const int tid = threadIdx.x;
  const int wid = tid >> 5, lane = tid & 31;
  const int n = blockIdx.y;
  const int t0 = blockIdx.x * 4;

  for (int i = tid; i < 3200; i += 512) ((uint4*)smc)[i] = make_uint4(0,0,0,0);

  for (int i = tid; i < 1875; i += 512) {
    int h = i / 625, r = i - h*625;
    int u = r / 25, v = r - (r/25)*25;
    satt[(h*25 + u)*28 + v] = g_att[(size_t)n*1875 + i];
  }
  for (int i = tid; i < 225; i += 512) { int row = i/3, c = 25 + (i - (i/3)*3); satt[row*28 + c] = 0.f; }

  {
    const float* xg = x + (((size_t)n*C_)*T_ + t0)*V_;
    for (int i = tid; i < 6400; i += 512) {
      int ci = i / 100, r = i - ci*100;
      sx[ci*101 + r] = xg[(size_t)ci*3200 + r];
    }
  }
  __syncthreads();

  // Phase 1: y[ch][t4][v] -> A[t4*32 + v + 2][ch] as fp16 (LDS.128 att reads)
  #pragma unroll
  for (int rep = 0; rep < 2; ++rep) {
    int task = tid + 512*rep;
    if (task < 768) {
      int h = task >> 8, t4 = (task >> 6) & 3, ci = task & 63;
      ull a2[13];
      #pragma unroll
      for (int j = 0; j < 13; ++j) a2[j] = 0ULL;
      const float* sxp = sx + ci*101 + t4*25;
      const float* ap0 = satt + h*25*28;
      #pragma unroll
      for (int u = 0; u < 25; ++u) {
        float xv = sxp[u];
        ull xp = pack2(xv, xv);
        const float* arow = ap0 + u*28;
        const ulonglong2* ar2 = (const ulonglong2*)arow;
        #pragma unroll
        for (int q = 0; q < 6; ++q) {
          ulonglong2 w = ar2[q];
          fma2(a2[2*q],   xp, w.x);
          fma2(a2[2*q+1], xp, w.y);
        }
        fma2(a2[12], xp, ((const ull*)arow)[12]);
      }
      const int ch = h*64 + ci;
      char* aro = smc + (t4*32 + 2)*400 + ch*2;
      #pragma unroll
      for (int v = 0; v < 25; ++v) {
        float yv = (v & 1) ? hi2(a2[v >> 1]) : lo2(a2[v >> 1]);
        *(__half*)(aro + v*400) = __float2half(yv);
      }
    }
  }
  __syncthreads();

  for (int i = tid; i < 3200; i += 512) {
    int b = i >= 1600;
    ((uint4*)(smc + 51200))[i] = g_Wimg[b][i - b*1600];
  }
  __syncthreads();

  // Phase 2: conv GEMM (single fp16 term), cp.async pipelined B reload
  const int mband = wid >> 1, nhalf = wid & 1;
  const int r8 = lane & 7;
  const uint32_t aoff  = (uint32_t)((mband*16 + r8 + ((lane>>3)&1)*8)*400 + (lane>>4)*16);
  const uint32_t boff0 = (uint32_t)((nhalf*32 + r8 + ((lane>>4)&1)*8)*400 + ((lane>>3)&1)*16);

  float d[4][4];
  #pragma unroll
  for (int j = 0; j < 4; ++j)
    #pragma unroll
    for (int k = 0; k < 4; ++k) d[j][k] = 0.f;

  for (int dv = 0; dv < 5; ++dv) {
    const int b = dv & 1;
    if (dv >= 2) {
      if (dv == 4) asm volatile("cp.async.wait_group 0;" ::: "memory");
      else         asm volatile("cp.async.wait_group 1;" ::: "memory");
      __syncthreads();
    }
    const uint32_t abase = sbase + aoff + (uint32_t)dv*400u;
    const uint32_t bbase = sbase + 51200u + (uint32_t)b*25600u + boff0;
    #pragma unroll
    for (int kc = 0; kc < 12; ++kc) {
      uint32_t ah[4], b0[4], b1[4];
      ldm_x4(ah, abase + kc*32);
      ldm_x4(b0, bbase + kc*32);
      ldm_x4(b1, bbase + 6400 + kc*32);
      mma_f16(d[0], ah, b0);
      mma_f16(d[1], ah, b0 + 2);
      mma_f16(d[2], ah, b1);
      mma_f16(d[3], ah, b1 + 2);
    }
    if (dv < 3) {
      __syncthreads();   // everyone done reading buffer b
      const uint32_t dst = sbase + 51200u + (uint32_t)b*25600u;
      for (int i = tid; i < 1600; i += 512)
        cp_async16(dst + (uint32_t)i*16u, &g_Wimg[dv + 2][i]);
      asm volatile("cp.async.commit_group;" ::: "memory");
    }
  }

  // Epilogue: predicated direct stores with bias + BN partial sums
  float bs[8], bq[8];
  {
    const int g = lane >> 2;
    const int m0 = mband*16 + g;
    const int m1 = m0 + 8;
    const int t40 = m0 >> 5, v0 = m0 & 31;
    const int t41 = m1 >> 5, v1 = m1 & 31;
    const size_t zb = (size_t)n*204800;
    #pragma unroll
    for (int j = 0; j < 4; ++j) {
      int co = nhalf*32 + j*8 + (lane & 3)*2;
      float b0v = bout[co], b1v = bout[co + 1];
      float s0 = 0.f, q0 = 0.f, s1 = 0.f, q1 = 0.f;
      if (v0 < 25) {
        size_t base = zb + (size_t)co*3200 + (t0 + t40)*25 + v0;
        float z0 = d[j][0] + b0v, z1 = d[j][1] + b1v;
        g_z[base]        = z0;
        g_z[base + 3200] = z1;
        s0 += z0; q0 += z0*z0; s1 += z1; q1 += z1*z1;
      }
      if (v1 < 25) {
        size_t base = zb + (size_t)co*3200 + (t0 + t41)*25 + v1;
        float z2 = d[j][2] + b0v, z3 = d[j][3] + b1v;
        g_z[base]        = z2;
        g_z[base + 3200] = z3;
        s0 += z2; q0 += z2*z2; s1 += z3; q1 += z3*z3;
      }
      bs[2*j] = s0; bq[2*j] = q0; bs[2*j+1] = s1; bq[2*j+1] = q1;
    }
  }
  #pragma unroll
  for (int off = 4; off <= 16; off <<= 1) {
    #pragma unroll
    for (int k = 0; k < 8; ++k) {
      bs[k] += __shfl_xor_sync(0xffffffffu, bs[k], off);
      bq[k] += __shfl_xor_sync(0xffffffffu, bq[k], off);
    }
  }
  __syncthreads();
  float* sred  = (float*)smc;
  float* sred2 = (float*)(smc + 4096);
  if ((lane >> 2) == 0) {
    #pragma unroll
    for (int j = 0; j < 4; ++j) {
      int col = nhalf*32 + j*8 + (lane & 3)*2;
      sred[wid*64 + col]      = bs[2*j];
      sred[wid*64 + col + 1]  = bs[2*j+1];
      sred2[wid*64 + col]     = bq[2*j];
      sred2[wid*64 + col + 1] = bq[2*j+1];
    }
  }
  __syncthreads();
  {
    const int cta = blockIdx.y*32 + blockIdx.x;
    if (tid < 64) {
      float s = 0.f;
      #pragma unroll
      for (int r = 0; r < 16; ++r) s += sred[r*64 + tid];
      g_bnpart[(size_t)cta*128 + tid] = s;
    } else if (tid < 128) {
      float s = 0.f;
      #pragma unroll
      for (int r = 0; r < 16; ++r) s += sred2[r*64 + tid - 64];
      g_bnpart[(size_t)cta*128 + tid] = s;
    }
  }
}

// ---------------- kernel C: BN reduce (2048 CTA partials) ----------------
__global__ void k_bnred(const float* __restrict__ gamma, const float* __restrict__ beta) {
  __shared__ float s[4][128];
  __shared__ float tot[128];
  const int tid = threadIdx.x;           // 512
  const int slot = tid & 127, part = tid >> 7;
  float sum = 0.f;
  for (int b = part; b < 2048; b += 4) sum += g_bnpart[(size_t)b*128 + slot];
  s[part][slot] = sum;
  __syncthreads();
  if (tid < 128) tot[tid] = s[0][tid] + s[1][tid] + s[2][tid] + s[3][tid];
  __syncthreads();
  if (tid < 64) {
    const float inv = 1.0f / 204800.0f;
    float mean = tot[tid] * inv;
    float var  = tot[64 + tid] * inv - mean*mean;
    float a = gamma[tid] * rsqrtf(var + 1e-5f);
    g_bn[tid]      = a;
    g_bn[64 + tid] = beta[tid] - mean * a;
  }
}

// ---------------- kernel D: epilogue ----------------
__global__ void k_out(const float* __restrict__ x, float* __restrict__ out) {
  const float4* z4 = (const float4*)g_z;
  const float4* x4 = (const float4*)x;
  float4* o4 = (float4*)out;
  const int total = (N_*C_*T_*V_) / 4;
  for (int i = blockIdx.x*blockDim.x + threadIdx.x; i < total; i += gridDim.x*blockDim.x) {
    int c = (i / 800) & 63;
    float a = g_bn[c], b = g_bn[64 + c];
    float4 z = z4[i], xx = x4[i], r;
    float v;
    v = z.x*a + b + xx.x; r.x = fmaxf(v, 0.1f*v);
    v = z.y*a + b + xx.y; r.y = fmaxf(v, 0.1f*v);
    v = z.z*a + b + xx.z; r.z = fmaxf(v, 0.1f*v);
    v = z.w*a + b + xx.w; r.w = fmaxf(v, 0.1f*v);
    o4[i] = r;
  }
}

// ---------------- launch ----------------
extern "C" void kernel_launch(void* const* d_in, const int* in_sizes, int n_in,
                              void* d_out, int out_size) {
  const float* x      = (const float*)d_in[0];
  const float* Wqkv   = (const float*)d_in[1];
  const float* bqkv   = (const float*)d_in[2];
  const float* alphas = (const float*)d_in[3];
  const float* att0s  = (const float*)d_in[4];
  const float* Wout   = (const float*)d_in[5];
  const float* bout   = (const float*)d_in[6];
  const float* gamma  = (const float*)d_in[7];
  const float* beta   = (const float*)d_in[8];
  float* out = (float*)d_out;

  cudaFuncSetAttribute(k_qkatt, cudaFuncAttributeMaxDynamicSharedMemorySize, 168960);
  cudaFuncSetAttribute(k_main,  cudaFuncAttributeMaxDynamicSharedMemorySize, 110800);

  k_init<<<64, 256>>>(Wqkv, Wout);
  k_qkatt<<<dim3(8, 64), 384, 168960>>>(x, bqkv);
  k_att2<<<(N_*1875 + 255)/256, 256>>>(alphas, att0s);
  k_main<<<dim3(32, 64), 512, 110800>>>(x, bout);
  k_bnred<<<1, 512>>>(gamma, beta);
  k_out<<<4096, 256>>>(x, out);
}

// round 17
// speedup vs baseline: 1.3633x; 1.0620x over previous
#include <cuda_runtime.h>
#include <cuda_bf16.h>
#include <cuda_fp16.h>
#include <cstdint>

#define N_  64
#define C_  64
#define T_  128
#define V_  25
#define H_  3
#define O_  192

typedef unsigned long long ull;

// ---------------- scratch ----------------
__device__ __align__(16) float g_pe[C_*V_];
__device__ __align__(16) float g_attpart[64*8*300*26];
__device__ __align__(16) float g_att[N_*H_*V_*V_];
__device__ __align__(16) float g_z[N_*C_*T_*V_];
__device__ __align__(16) float g_bnpart[2048*128];
__device__ __align__(16) float g_bn[128];
// conv W per dv: [co=64][colp=200] fp16 = 25600 B = 1600 uint4
__device__ __align__(16) uint4 g_Wimg[5][1600];
// QKV W image: [term hi/lo][o=192][c=72pad] fp16 = 55296 B = 3456 uint4
__device__ __align__(16) uint4 g_WqkvImg[3456];

// ---------------- f32x2 helpers ----------------
static __device__ __forceinline__ ull pack2(float a, float b){
  ull r; asm("mov.b64 %0, {%1, %2};" : "=l"(r) : "f"(a), "f"(b)); return r;
}
static __device__ __forceinline__ void fma2(ull& d, ull a, ull b){
  asm("fma.rn.f32x2 %0, %1, %2, %0;" : "+l"(d) : "l"(a), "l"(b));
}
static __device__ __forceinline__ float lo2(ull v){ return __uint_as_float((unsigned)v); }
static __device__ __forceinline__ float hi2(ull v){ return __uint_as_float((unsigned)(v>>32)); }

// ---------------- portable tensor-core helpers (sm_80+ baseline PTX) ----------------
static __device__ __forceinline__ uint32_t smem_to_u32(const void* p) {
  uint32_t a;
  asm("{ .reg .u64 t; cvta.to.shared.u64 t, %1; cvt.u32.u64 %0, t; }" : "=r"(a) : "l"(p));
  return a;
}
static __device__ __forceinline__ void ldm_x4(uint32_t* r, uint32_t addr){
  asm volatile("ldmatrix.sync.aligned.m8n8.x4.shared.b16 {%0,%1,%2,%3}, [%4];"
    : "=r"(r[0]), "=r"(r[1]), "=r"(r[2]), "=r"(r[3]) : "r"(addr));
}
static __device__ __forceinline__ void mma_f16(float* d, const uint32_t* a, const uint32_t* b){
  asm volatile("mma.sync.aligned.m16n8k16.row.col.f32.f16.f16.f32 "
    "{%0,%1,%2,%3}, {%4,%5,%6,%7}, {%8,%9}, {%0,%1,%2,%3};"
    : "+f"(d[0]), "+f"(d[1]), "+f"(d[2]), "+f"(d[3])
    : "r"(a[0]), "r"(a[1]), "r"(a[2]), "r"(a[3]), "r"(b[0]), "r"(b[1]));
}
static __device__ __forceinline__ void cp_async16(uint32_t smem_dst, const void* gsrc){
  asm volatile("cp.async.cg.shared.global [%0], [%1], 16;"
    :: "r"(smem_dst), "l"(gsrc) : "memory");
}

// ---------------- init ----------------
__global__ void k_init(const float* __restrict__ Wqkv, const float* __restrict__ Wout) {
  const int stride = gridDim.x * blockDim.x;
  const int i0 = blockIdx.x * blockDim.x + threadIdx.x;
  for (int i = i0; i < C_*V_; i += stride) {
    int c = i / V_, v = i - (i / V_) * V_;
    int ii = c >> 1;
    float dv = __expf(-(2.0f * ii) * (logf(10000.0f) / 64.0f));
    float ang = (float)v * dv;
    g_pe[i] = (c & 1) ? cosf(ang) : sinf(ang);
  }
  {
    __half* wb = (__half*)g_WqkvImg;
    for (int i = i0; i < 2*192*72; i += stride) {
      int term = i / 13824; int r = i - term*13824;
      int o = r / 72, c = r - (r/72)*72;
      float w = (c < 64) ? Wqkv[o*64 + c] : 0.f;
      __half hb = __float2half(w);
      wb[i] = (term == 0) ? hb : __float2half(w - __half2float(hb));
    }
  }
  {
    __half* wb = (__half*)g_Wimg;
    for (int i = i0; i < 5*64*200; i += stride) {
      int dv = i / 12800; int r = i - dv*12800;
      int co = r / 200; int cp = r - co*200;
      float w = (cp < 192) ? Wout[co*960 + cp*5 + dv] : 0.f;
      wb[i] = __float2half(w);
    }
  }
}

// ---------------- kernel A: QK GEMM (mma.sync fp16 3-term) + scalar Gram ----------------
// smem 113664 B -> 2 CTAs/SM:
//   qk fp32 @0 (192 x QKP=106 = 81408 B; W images staged here temporarily)
//   xs hi @81408, xs lo @97536 (16128 B each)
// Per-p accumulator (8 regs) + immediate qk write keeps regs under the 2-CTA cap.
#define QKP 106
__global__ __launch_bounds__(384, 2) void k_qkatt(const float* __restrict__ x,
                                                  const float* __restrict__ bqkv) {
  extern __shared__ char sqc[];
  const uint32_t sbase = smem_to_u32(sqc);
  float* qk = (float*)sqc;
  const int tid = threadIdx.x;
  const int wid = tid >> 5, lane = tid & 31;
  const int n = blockIdx.y, tc = blockIdx.x;
  const int t0 = tc * 16;

  // stage W images @0 (temp; clobbered by qk after fragment hoist)
  for (int i = tid; i < 3456; i += 384) ((uint4*)sqc)[i] = g_WqkvImg[i];

  // stage xs chunk 0 @81408/@97536
  {
    const float* xg = x + (((size_t)n*C_)*T_ + t0)*V_;
    for (int i = tid; i < 6400; i += 384) {
      int c = (i & 7) | (((i >> 5) & 7) << 3);
      int r = ((i >> 3) & 3) | ((i >> 8) << 2);
      int tl = r / 25, v = r - tl*25;
      float xv = xg[(size_t)c*3200 + r] + g_pe[c*25 + v];
      int boff = (tl*26 + v)*144 + c*2;
      __half hb = __float2half(xv);
      *(__half*)(sqc + 81408 + boff) = hb;
      *(__half*)(sqc + 97536 + boff) = __float2half(xv - __half2float(hb));
    }
  }
  __syncthreads();

  const int m0 = wid * 16;
  const uint32_t aoff = (uint32_t)((m0 + (lane&7) + ((lane>>3)&1)*8)*144 + (lane>>4)*16);
  uint32_t ah[4][4], al[4][4];
  #pragma unroll
  for (int kc = 0; kc < 4; ++kc) {
    ldm_x4(ah[kc], sbase + aoff + kc*32);
    ldm_x4(al[kc], sbase + 27648u + aoff + kc*32);
  }
  __syncthreads();   // W region free only after ALL warps hoisted fragments

  const int g = lane >> 2, c0 = (lane&3)*2;
  const float bq0 = bqkv[m0 + g];
  const float bq1 = bqkv[m0 + g + 8];

  const int grow = tid >> 2, gcq = tid & 3;
  const bool gact = (tid < 300);
  const int gh = grow / 25, gu = grow - (grow/25)*25;
  ull gacc[13];
  #pragma unroll
  for (int j = 0; j < 13; ++j) gacc[j] = 0ULL;

  const uint32_t bboff = (uint32_t)(((lane&7) + ((lane>>4)&1)*8)*144 + ((lane>>3)&1)*16);

  for (int ck = 0; ck < 4; ++ck) {
    #pragma unroll
    for (int p = 0; p < 7; ++p) {
      float d0[4] = {0.f, 0.f, 0.f, 0.f};
      float d1[4] = {0.f, 0.f, 0.f, 0.f};
      const uint32_t bb = sbase + 81408u + (uint32_t)p*2304u + bboff;
      #pragma unroll
      for (int kc = 0; kc < 4; ++kc) {
        uint32_t bh[4], bl[4];
        ldm_x4(bh, bb + kc*32);
        ldm_x4(bl, bb + 16128u + kc*32);
        mma_f16(d0, ah[kc], bh);
        mma_f16(d1, ah[kc], bh + 2);
        mma_f16(d0, ah[kc], bl);
        mma_f16(d1, ah[kc], bl + 2);
        mma_f16(d0, al[kc], bh);
        mma_f16(d1, al[kc], bh + 2);
      }
      // write nt = 2p (always) and 2p+1 (skip pad tile nt=13)
      {
        int col = (2*p)*8 + c0;
        float* r0 = qk + (m0 + g)*QKP + col;
        float* r1 = qk + (m0 + g + 8)*QKP + col;
        r0[0] = d0[0] + bq0; r0[1] = d0[1] + bq0;
        r1[0] = d0[2] + bq1; r1[1] = d0[3] + bq1;
      }
      if (p < 6) {
        int col = (2*p + 1)*8 + c0;
        float* r0 = qk + (m0 + g)*QKP + col;
        float* r1 = qk + (m0 + g + 8)*QKP + col;
        r0[0] = d1[0] + bq0; r0[1] = d1[1] + bq0;
        r1[0] = d1[2] + bq1; r1[1] = d1[3] + bq1;
      }
    }
    __syncthreads();

    if (gact) {
      #pragma unroll
      for (int tl = 0; tl < 4; ++tl) {
        #pragma unroll
        for (int c8 = 0; c8 < 8; ++c8) {
          int c = gcq*8 + c8;
          float qv = qk[(gh*32 + c)*QKP + tl*26 + gu];
          ull q2 = pack2(qv, qv);
          const ull* kp = (const ull*)(qk + (96 + gh*32 + c)*QKP) + tl*13;
          #pragma unroll
          for (int j = 0; j < 13; ++j) fma2(gacc[j], q2, kp[j]);
        }
      }
    }
    if (ck < 3) {
      const float* xg = x + (((size_t)n*C_)*T_ + t0 + (ck+1)*4)*V_;
      for (int i = tid; i < 6400; i += 384) {
        int c = (i & 7) | (((i >> 5) & 7) << 3);
        int r = ((i >> 3) & 3) | ((i >> 8) << 2);
        int tl = r / 25, v = r - tl*25;
        float xv = xg[(size_t)c*3200 + r] + g_pe[c*25 + v];
        int boff = (tl*26 + v)*144 + c*2;
        __half hb = __float2half(xv);
        *(__half*)(sqc + 81408 + boff) = hb;
        *(__half*)(sqc + 97536 + boff) = __float2half(xv - __half2float(hb));
      }
    }
    __syncthreads();
  }

  if (gact) {
    ull* op = (ull*)(g_attpart + ((size_t)(n*8 + tc)*300 + tid)*26);
    #pragma unroll
    for (int j = 0; j < 13; ++j) op[j] = gacc[j];
  }
}

// ---------------- kernel A2 ----------------
__global__ void k_att2(const float* __restrict__ alphas, const float* __restrict__ att0s) {
  int i = blockIdx.x * blockDim.x + threadIdx.x;
  if (i >= N_*1875) return;
  int n = i / 1875, r = i - n*1875;
  int h = r / 625, rr = r - h*625;
  int u = rr / 25, v = rr - (rr/25)*25;
  int row = h*25 + u;
  float s = 0.f;
  #pragma unroll
  for (int tc = 0; tc < 8; ++tc)
    #pragma unroll
    for (int cq = 0; cq < 4; ++cq)
      s += g_attpart[((size_t)(n*8 + tc)*300 + row*4 + cq)*26 + v];
  g_att[i] = tanhf(s * (1.0f/4096.0f)) * alphas[h] + att0s[r];
}

// ---------------- kernel B: att-apply (FFMA2) + conv (mma.sync fp16) + BN partials ----------------
// grid (32 tc, 64 n), 512 threads, 2 CTAs/SM. smem total 110800 B.
// B reload pipelined with cp.async (one-iteration lookahead).
__global__ __launch_bounds__(512, 2) void k_main(const float* __restrict__ x,
                                                 const float* __restrict__ bout) {
  extern __shared__ char smc[];
  const uint32_t sbase = smem_to_u32(smc);
  float* satt = (float*)(smc + 102400);
  float* sx   = (float*)(smc + 51200);

  const int tid = threadIdx.x;
  const int wid = tid >> 5, lane = tid & 31;
  const int n = blockIdx.y;
  const int t0 = blockIdx.x * 4;

  for (int i = tid; i < 3200; i += 512) ((uint4*)smc)[i] = make_uint4(0,0,0,0);

  for (int i = tid; i < 1875; i += 512) {
    int h = i / 625, r = i - h*625;
    int u = r / 25, v = r - (r/25)*25;
    satt[(h*25 + u)*28 + v] = g_att[(size_t)n*1875 + i];
  }
  for (int i = tid; i < 225; i += 512) { int row = i/3, c = 25 + (i - (i/3)*3); satt[row*28 + c] = 0.f; }

  {
    const float* xg = x + (((size_t)n*C_)*T_ + t0)*V_;
    for (int i = tid; i < 6400; i += 512) {
      int ci = i / 100, r = i - ci*100;
      sx[ci*101 + r] = xg[(size_t)ci*3200 + r];
    }
  }
  __syncthreads();

  // Phase 1: y[ch][t4][v] -> A[t4*32 + v + 2][ch] as fp16 (LDS.128 att reads)
  #pragma unroll
  for (int rep = 0; rep < 2; ++rep) {
    int task = tid + 512*rep;
    if (task < 768) {
      int h = task >> 8, t4 = (task >> 6) & 3, ci = task & 63;
      ull a2[13];
      #pragma unroll
      for (int j = 0; j < 13; ++j) a2[j] = 0ULL;
      const float* sxp = sx + ci*101 + t4*25;
      const float* ap0 = satt + h*25*28;
      #pragma unroll
      for (int u = 0; u < 25; ++u) {
        float xv = sxp[u];
        ull xp = pack2(xv, xv);
        const float* arow = ap0 + u*28;
        const ulonglong2* ar2 = (const ulonglong2*)arow;
        #pragma unroll
        for (int q = 0; q < 6; ++q) {
          ulonglong2 w = ar2[q];
          fma2(a2[2*q],   xp, w.x);
          fma2(a2[2*q+1], xp, w.y);
        }
        fma2(a2[12], xp, ((const ull*)arow)[12]);
      }
      const int ch = h*64 + ci;
      char* aro = smc + (t4*32 + 2)*400 + ch*2;
      #pragma unroll
      for (int v = 0; v < 25; ++v) {
        float yv = (v & 1) ? hi2(a2[v >> 1]) : lo2(a2[v >> 1]);
        *(__half*)(aro + v*400) = __float2half(yv);
      }
    }
  }
  __syncthreads();

  for (int i = tid; i < 3200; i += 512) {
    int b = i >= 1600;
    ((uint4*)(smc + 51200))[i] = g_Wimg[b][i - b*1600];
  }
  __syncthreads();

  // Phase 2: conv GEMM (single fp16 term), cp.async pipelined B reload
  const int mband = wid >> 1, nhalf = wid & 1;
  const int r8 = lane & 7;
  const uint32_t aoff  = (uint32_t)((mband*16 + r8 + ((lane>>3)&1)*8)*400 + (lane>>4)*16);
  const uint32_t boff0 = (uint32_t)((nhalf*32 + r8 + ((lane>>4)&1)*8)*400 + ((lane>>3)&1)*16);

  float d[4][4];
  #pragma unroll
  for (int j = 0; j < 4; ++j)
    #pragma unroll
    for (int k = 0; k < 4; ++k) d[j][k] = 0.f;

  for (int dv = 0; dv < 5; ++dv) {
    const int b = dv & 1;
    if (dv >= 2) {
      if (dv == 4) asm volatile("cp.async.wait_group 0;" ::: "memory");
      else         asm volatile("cp.async.wait_group 1;" ::: "memory");
      __syncthreads();
    }
    const uint32_t abase = sbase + aoff + (uint32_t)dv*400u;
    const uint32_t bbase = sbase + 51200u + (uint32_t)b*25600u + boff0;
    #pragma unroll
    for (int kc = 0; kc < 12; ++kc) {
      uint32_t ah[4], b0[4], b1[4];
      ldm_x4(ah, abase + kc*32);
      ldm_x4(b0, bbase + kc*32);
      ldm_x4(b1, bbase + 6400 + kc*32);
      mma_f16(d[0], ah, b0);
      mma_f16(d[1], ah, b0 + 2);
      mma_f16(d[2], ah, b1);
      mma_f16(d[3], ah, b1 + 2);
    }
    if (dv < 3) {
      __syncthreads();   // everyone done reading buffer b
      const uint32_t dst = sbase + 51200u + (uint32_t)b*25600u;
      for (int i = tid; i < 1600; i += 512)
        cp_async16(dst + (uint32_t)i*16u, &g_Wimg[dv + 2][i]);
      asm volatile("cp.async.commit_group;" ::: "memory");
    }
  }

  // Epilogue: predicated direct stores with bias + BN partial sums
  float bs[8], bq[8];
  {
    const int g = lane >> 2;
    const int m0 = mband*16 + g;
    const int m1 = m0 + 8;
    const int t40 = m0 >> 5, v0 = m0 & 31;
    const int t41 = m1 >> 5, v1 = m1 & 31;
    const size_t zb = (size_t)n*204800;
    #pragma unroll
    for (int j = 0; j < 4; ++j) {
      int co = nhalf*32 + j*8 + (lane & 3)*2;
      float b0v = bout[co], b1v = bout[co + 1];
      float s0 = 0.f, q0 = 0.f, s1 = 0.f, q1 = 0.f;
      if (v0 < 25) {
        size_t base = zb + (size_t)co*3200 + (t0 + t40)*25 + v0;
        float z0 = d[j][0] + b0v, z1 = d[j][1] + b1v;
        g_z[base]        = z0;
        g_z[base + 3200] = z1;
        s0 += z0; q0 += z0*z0; s1 += z1; q1 += z1*z1;
      }
      if (v1 < 25) {
        size_t base = zb + (size_t)co*3200 + (t0 + t41)*25 + v1;
        float z2 = d[j][2] + b0v, z3 = d[j][3] + b1v;
        g_z[base]        = z2;
        g_z[base + 3200] = z3;
        s0 += z2; q0 += z2*z2; s1 += z3; q1 += z3*z3;
      }
      bs[2*j] = s0; bq[2*j] = q0; bs[2*j+1] = s1; bq[2*j+1] = q1;
    }
  }
  #pragma unroll
  for (int off = 4; off <= 16; off <<= 1) {
    #pragma unroll
    for (int k = 0; k < 8; ++k) {
      bs[k] += __shfl_xor_sync(0xffffffffu, bs[k], off);
      bq[k] += __shfl_xor_sync(0xffffffffu, bq[k], off);
    }
  }
  __syncthreads();
  float* sred  = (float*)smc;
  float* sred2 = (float*)(smc + 4096);
  if ((lane >> 2) == 0) {
    #pragma unroll
    for (int j = 0; j < 4; ++j) {
      int col = nhalf*32 + j*8 + (lane & 3)*2;
      sred[wid*64 + col]      = bs[2*j];
      sred[wid*64 + col + 1]  = bs[2*j+1];
      sred2[wid*64 + col]     = bq[2*j];
      sred2[wid*64 + col + 1] = bq[2*j+1];
    }
  }
  __syncthreads();
  {
    const int cta = blockIdx.y*32 + blockIdx.x;
    if (tid < 64) {
      float s = 0.f;
      #pragma unroll
      for (int r = 0; r < 16; ++r) s += sred[r*64 + tid];
      g_bnpart[(size_t)cta*128 + tid] = s;
    } else if (tid < 128) {
      float s = 0.f;
      #pragma unroll
      for (int r = 0; r < 16; ++r) s += sred2[r*64 + tid - 64];
      g_bnpart[(size_t)cta*128 + tid] = s;
    }
  }
}

// ---------------- kernel C: BN reduce (2048 CTA partials) ----------------
__global__ void k_bnred(const float* __restrict__ gamma, const float* __restrict__ beta) {
  __shared__ float s[4][128];
  __shared__ float tot[128];
  const int tid = threadIdx.x;           // 512
  const int slot = tid & 127, part = tid >> 7;
  float sum = 0.f;
  for (int b = part; b < 2048; b += 4) sum += g_bnpart[(size_t)b*128 + slot];
  s[part][slot] = sum;
  __syncthreads();
  if (tid < 128) tot[tid] = s[0][tid] + s[1][tid] + s[2][tid] + s[3][tid];
  __syncthreads();
  if (tid < 64) {
    const float inv = 1.0f / 204800.0f;
    float mean = tot[tid] * inv;
    float var  = tot[64 + tid] * inv - mean*mean;
    float a = gamma[tid] * rsqrtf(var + 1e-5f);
    g_bn[tid]      = a;
    g_bn[64 + tid] = beta[tid] - mean * a;
  }
}

// ---------------- kernel D: epilogue ----------------
__global__ void k_out(const float* __restrict__ x, float* __restrict__ out) {
  const float4* z4 = (const float4*)g_z;
  const float4* x4 = (const float4*)x;
  float4* o4 = (float4*)out;
  const int total = (N_*C_*T_*V_) / 4;
  for (int i = blockIdx.x*blockDim.x + threadIdx.x; i < total; i += gridDim.x*blockDim.x) {
    int c = (i / 800) & 63;
    float a = g_bn[c], b = g_bn[64 + c];
    float4 z = z4[i], xx = x4[i], r;
    float v;
    v = z.x*a + b + xx.x; r.x = fmaxf(v, 0.1f*v);
    v = z.y*a + b + xx.y; r.y = fmaxf(v, 0.1f*v);
    v = z.z*a + b + xx.z; r.z = fmaxf(v, 0.1f*v);
    v = z.w*a + b + xx.w; r.w = fmaxf(v, 0.1f*v);
    o4[i] = r;
  }
}

// ---------------- launch ----------------
extern "C" void kernel_launch(void* const* d_in, const int* in_sizes, int n_in,
                              void* d_out, int out_size) {
  const float* x      = (const float*)d_in[0];
  const float* Wqkv   = (const float*)d_in[1];
  const float* bqkv   = (const float*)d_in[2];
  const float* alphas = (const float*)d_in[3];
  const float* att0s  = (const float*)d_in[4];
  const float* Wout   = (const float*)d_in[5];
  const float* bout   = (const float*)d_in[6];
  const float* gamma  = (const float*)d_in[7];
  const float* beta   = (const float*)d_in[8];
  float* out = (float*)d_out;

  cudaFuncSetAttribute(k_qkatt, cudaFuncAttributeMaxDynamicSharedMemorySize, 113664);
  cudaFuncSetAttribute(k_main,  cudaFuncAttributeMaxDynamicSharedMemorySize, 110800);

  k_init<<<64, 256>>>(Wqkv, Wout);
  k_qkatt<<<dim3(8, 64), 384, 113664>>>(x, bqkv);
  k_att2<<<(N_*1875 + 255)/256, 256>>>(alphas, att0s);
  k_main<<<dim3(32, 64), 512, 110800>>>(x, bout);
  k_bnred<<<1, 512>>>(gamma, beta);
  k_out<<<4096, 256>>>(x, out);
}